// round 4
// baseline (speedup 1.0000x reference)
#include <cuda_runtime.h>

// out[b, f, s] = x[b, 0, s] * w[f, s] + bias[f, s]
// B=128, F=256, S=4096. HBM-write-bound: 512 MiB out @ ~6.4 TB/s store stream.
//
// R4: BT=8 (was 16) to cut regs 128 -> ~80 => 3 CTAs/SM (occ ~37%), FT=16 to
// keep read amplification low (0.31 read bytes per write byte, all inputs
// L2-resident anyway). Testing whether store MLP (occupancy) lifts DRAM%.

#define BATCH 128
#define NFILT 256
#define SLEN  4096
#define FT    16          // filters per block
#define BT    8           // batches per block
#define CHUNK4 256        // float4 per s-chunk (1024 floats), one per thread

__global__ __launch_bounds__(256, 3) void dense_filter_expand_kernel(
    const float4* __restrict__ x,     // [B, S/4]
    const float4* __restrict__ w,     // [F, S/4]
    const float4* __restrict__ bias,  // [F, S/4]
    float4* __restrict__ out)         // [B, F, S/4]
{
    const int S4 = SLEN / 4;                   // 1024 float4 per row
    const int t  = threadIdx.x;                // 0..255
    const int sc = blockIdx.x;                 // 0..3   s-chunk
    const int fg = blockIdx.y;                 // 0..15  filter group
    const int bg = blockIdx.z;                 // 0..15  batch group
    const int s4 = sc * CHUNK4 + t;            // float4 index within a row
    const int b0 = bg * BT;
    const int f0 = fg * FT;

    // Register-cache x for the 8 batches in this group (32 regs).
    float4 xv[BT];
#pragma unroll
    for (int i = 0; i < BT; i++)
        xv[i] = __ldg(&x[(size_t)(b0 + i) * S4 + s4]);

#pragma unroll 1
    for (int ff = 0; ff < FT; ff++) {
        const int f = f0 + ff;
        const float4 wv = __ldg(&w[(size_t)f * S4 + s4]);
        const float4 bv = __ldg(&bias[(size_t)f * S4 + s4]);

#pragma unroll
        for (int i = 0; i < BT; i++) {
            float4 o;
            o.x = fmaf(xv[i].x, wv.x, bv.x);
            o.y = fmaf(xv[i].y, wv.y, bv.y);
            o.z = fmaf(xv[i].z, wv.z, bv.z);
            o.w = fmaf(xv[i].w, wv.w, bv.w);
            // Streaming store: output is write-once, never re-read.
            __stcs(&out[((size_t)(b0 + i) * NFILT + f) * S4 + s4], o);
        }
    }
}

extern "C" void kernel_launch(void* const* d_in, const int* in_sizes, int n_in,
                              void* d_out, int out_size) {
    const float4* x    = (const float4*)d_in[0];   // inputs [128,1,4096]
    const float4* w    = (const float4*)d_in[1];   // w [256,4096]
    const float4* bias = (const float4*)d_in[2];   // b [256,4096]
    float4* out = (float4*)d_out;

    dim3 grid(SLEN / (CHUNK4 * 4), NFILT / FT, BATCH / BT);  // (4, 16, 16) = 1024
    dense_filter_expand_kernel<<<grid, 256>>>(x, w, bias, out);
}

// round 5
// speedup vs baseline: 1.0796x; 1.0796x over previous
#include <cuda_runtime.h>

// out[b, f, s] = x[b, 0, s] * w[f, s] + bias[f, s]
// B=128, F=256, S=4096. HBM-write-bound: 512 MiB out.
//
// R5: R3 traffic profile (FT=8 filters cached in regs, BT=16 batches,
// read amp 0.25) but loops FLIPPED: batch outer, filter inner. Per batch
// iteration a CTA emits 8 x 4KB store bursts at 16KB stride (116KB window)
// instead of 16 bursts at 1MB stride -> better DRAM row locality.

#define BATCH 128
#define NFILT 256
#define SLEN  4096
#define FT    8           // filters per block (w/bias register-cached)
#define BT    16          // batches per block
#define CHUNK4 256        // float4 per s-chunk, one per thread

__global__ __launch_bounds__(256, 2) void dense_filter_expand_kernel(
    const float4* __restrict__ x,     // [B, S/4]
    const float4* __restrict__ w,     // [F, S/4]
    const float4* __restrict__ bias,  // [F, S/4]
    float4* __restrict__ out)         // [B, F, S/4]
{
    const int S4 = SLEN / 4;                   // 1024 float4 per row
    const int t  = threadIdx.x;                // 0..255
    const int sc = blockIdx.x;                 // 0..3   s-chunk
    const int fg = blockIdx.y;                 // 0..31  filter group
    const int bg = blockIdx.z;                 // 0..7   batch group
    const int s4 = sc * CHUNK4 + t;            // float4 index within a row
    const int b0 = bg * BT;
    const int f0 = fg * FT;

    // Register-cache w/bias chunks for the 8 filters (64 regs).
    float4 wv[FT], bv[FT];
#pragma unroll
    for (int ff = 0; ff < FT; ff++) {
        wv[ff] = __ldg(&w[(size_t)(f0 + ff) * S4 + s4]);
        bv[ff] = __ldg(&bias[(size_t)(f0 + ff) * S4 + s4]);
    }

#pragma unroll 1
    for (int bb = 0; bb < BT; bb++) {
        const int b = b0 + bb;
        const float4 xv = __ldg(&x[(size_t)b * S4 + s4]);

        // Base of out[b][f0][s4]; filter stride is S4 float4s (16 KB).
        float4* obase = out + ((size_t)b * NFILT + f0) * S4 + s4;

#pragma unroll
        for (int ff = 0; ff < FT; ff++) {
            float4 o;
            o.x = fmaf(xv.x, wv[ff].x, bv[ff].x);
            o.y = fmaf(xv.y, wv[ff].y, bv[ff].y);
            o.z = fmaf(xv.z, wv[ff].z, bv[ff].z);
            o.w = fmaf(xv.w, wv[ff].w, bv[ff].w);
            // Streaming store: output is write-once, never re-read.
            __stcs(obase + (size_t)ff * S4, o);
        }
    }
}

extern "C" void kernel_launch(void* const* d_in, const int* in_sizes, int n_in,
                              void* d_out, int out_size) {
    const float4* x    = (const float4*)d_in[0];   // inputs [128,1,4096]
    const float4* w    = (const float4*)d_in[1];   // w [256,4096]
    const float4* bias = (const float4*)d_in[2];   // b [256,4096]
    float4* out = (float4*)d_out;

    dim3 grid(SLEN / (CHUNK4 * 4), NFILT / FT, BATCH / BT);  // (4, 32, 8) = 1024
    dense_filter_expand_kernel<<<grid, 256>>>(x, w, bias, out);
}